// round 1
// baseline (speedup 1.0000x reference)
#include <cuda_runtime.h>
#include <cuda_bf16.h>
#include <cstdint>

// ---------------------------------------------------------------------------
// Problem dims (fixed)
// ---------------------------------------------------------------------------
#define BATCH   4
#define SEQ     4096
#define EMBED   1024
#define D1      1024
#define D2      2048          // 2*D1
#define FEAT    32
#define RPE_L   3
#define FFTLEN  8192          // 2*SEQ
#define M_TOT   (BATCH*SEQ)   // 16384

// ---------------------------------------------------------------------------
// Scratch (device globals; no runtime allocation allowed)
// ---------------------------------------------------------------------------
__device__ float  g_uv  [(size_t)M_TOT * D2];        // silu(x@W_uv): u = cols [0,1024), v = cols [1024,2048)
__device__ float  g_tT  [(size_t)D1 * SEQ];          // t transposed: [c][k]
__device__ float2 g_that[(size_t)D1 * FFTLEN];       // FFT(t) per channel, DIF bit-reversed order, scaled by 1/L
__device__ float  g_ot  [(size_t)BATCH * D1 * SEQ];  // o transposed: [b][c][n]

__device__ __forceinline__ float siluf(float x) { return x * (1.0f / (1.0f + __expf(-x))); }

// ---------------------------------------------------------------------------
// Kernel A: RPE MLP -> t_T[c][k], with per-channel decay gamma^k folded in
// grid 32, block 256.  Each block handles 128 consecutive positions.
// ---------------------------------------------------------------------------
__global__ __launch_bounds__(256) void rpe_kernel(
    const float* __restrict__ in_w,      // [1,32]
    const float* __restrict__ hid_w,     // [3,32,32]
    const float* __restrict__ ln_g,      // [3,32]
    const float* __restrict__ ln_b,      // [3,32]
    const float* __restrict__ out_w,     // [32,1024]
    const float* __restrict__ dgamma)    // [1024]
{
    __shared__ float hsh[128][FEAT + 1];
    const int tid = threadIdx.x;
    const int k0  = blockIdx.x * 128;

    if (tid < 128) {
        float kf = (float)(k0 + tid);
        float h[FEAT], hn[FEAT];
        #pragma unroll
        for (int f = 0; f < FEAT; ++f) h[f] = siluf(kf * in_w[f]);

        for (int layer = 0; layer < RPE_L; ++layer) {
            float mu = 0.0f;
            #pragma unroll
            for (int f = 0; f < FEAT; ++f) mu += h[f];
            mu *= (1.0f / FEAT);
            float var = 0.0f;
            #pragma unroll
            for (int f = 0; f < FEAT; ++f) { float d = h[f] - mu; var += d * d; }
            var *= (1.0f / FEAT);
            float inv = rsqrtf(var + 1e-5f);
            #pragma unroll
            for (int f = 0; f < FEAT; ++f)
                hn[f] = (h[f] - mu) * inv * ln_g[layer * FEAT + f] + ln_b[layer * FEAT + f];
            #pragma unroll
            for (int f2 = 0; f2 < FEAT; ++f2) {
                float acc = 0.0f;
                #pragma unroll
                for (int f = 0; f < FEAT; ++f)
                    acc += hn[f] * hid_w[layer * FEAT * FEAT + f * FEAT + f2];
                h[f2] = siluf(acc);
            }
        }
        #pragma unroll
        for (int f = 0; f < FEAT; ++f) hsh[tid][f] = h[f];
    }
    __syncthreads();

    for (int c = tid; c < D1; c += 256) {
        float w[FEAT];
        #pragma unroll
        for (int f = 0; f < FEAT; ++f) w[f] = out_w[f * D1 + c];
        float g  = 0.99f + 0.01f * (1.0f / (1.0f + __expf(-dgamma[c])));
        float lg = logf(g);
        float dec = expf((float)k0 * lg);
        for (int kk = 0; kk < 128; ++kk) {
            float acc = 0.0f;
            #pragma unroll
            for (int f = 0; f < FEAT; ++f) acc += hsh[kk][f] * w[f];
            g_tT[(size_t)c * SEQ + k0 + kk] = acc * dec;
            dec *= g;
        }
    }
}

// ---------------------------------------------------------------------------
// FFT helpers: radix-2, length 8192, 256 threads.
// Forward: DIF (natural in -> bit-reversed out), twiddle e^{-i pi j / h}.
// Inverse: DIT (bit-reversed in -> natural out), conj twiddles, unnormalized.
// Twiddle table Wt[j] = e^{-i pi j / 4096}, j in [0,4096).
// ---------------------------------------------------------------------------
__device__ __forceinline__ void fft_fill_table(float2* Wt, int tid) {
    for (int j = tid; j < SEQ; j += 256) {
        float s, c;
        sincosf(-3.14159265358979f * (float)j / (float)SEQ, &s, &c);
        Wt[j] = make_float2(c, s);
    }
}

__device__ __forceinline__ void fft_forward(float2* Z, const float2* Wt, int tid) {
    for (int s = 12; s >= 0; --s) {
        const int h = 1 << s;
        #pragma unroll 4
        for (int idx = tid; idx < SEQ; idx += 256) {
            int j  = idx & (h - 1);
            int i0 = ((idx - j) << 1) + j;
            float2 a = Z[i0], b = Z[i0 + h];
            float2 w = Wt[j << (12 - s)];
            float2 d = make_float2(a.x - b.x, a.y - b.y);
            Z[i0]     = make_float2(a.x + b.x, a.y + b.y);
            Z[i0 + h] = make_float2(d.x * w.x - d.y * w.y, d.x * w.y + d.y * w.x);
        }
        __syncthreads();
    }
}

__device__ __forceinline__ void fft_inverse(float2* Z, const float2* Wt, int tid) {
    for (int s = 0; s <= 12; ++s) {
        const int h = 1 << s;
        #pragma unroll 4
        for (int idx = tid; idx < SEQ; idx += 256) {
            int j  = idx & (h - 1);
            int i0 = ((idx - j) << 1) + j;
            float2 a = Z[i0], b = Z[i0 + h];
            float2 w = Wt[j << (12 - s)];
            // b * conj(w)
            float2 bw = make_float2(b.x * w.x + b.y * w.y, b.y * w.x - b.x * w.y);
            Z[i0]     = make_float2(a.x + bw.x, a.y + bw.y);
            Z[i0 + h] = make_float2(a.x - bw.x, a.y - bw.y);
        }
        __syncthreads();
    }
}

// ---------------------------------------------------------------------------
// Kernel B: that[c] = FFT(t[:,c] zero-padded) * (1/L)   (bit-reversed order)
// grid 1024, block 256, dyn smem 98304 B
// ---------------------------------------------------------------------------
__global__ __launch_bounds__(256) void fft_t_kernel()
{
    extern __shared__ float2 sh[];
    float2* Z  = sh;           // 8192
    float2* Wt = sh + FFTLEN;  // 4096
    const int c = blockIdx.x, tid = threadIdx.x;

    fft_fill_table(Wt, tid);
    for (int j = tid; j < SEQ; j += 256) {
        Z[j]       = make_float2(g_tT[(size_t)c * SEQ + j], 0.0f);
        Z[j + SEQ] = make_float2(0.0f, 0.0f);
    }
    __syncthreads();

    fft_forward(Z, Wt, tid);

    const float sc = 1.0f / (float)FFTLEN;
    for (int i = tid; i < FFTLEN; i += 256) {
        float2 z = Z[i];
        g_that[(size_t)c * FFTLEN + i] = make_float2(z.x * sc, z.y * sc);
    }
}

// ---------------------------------------------------------------------------
// Kernel C: per (b,c): o[b,:,c] = irfft( FFT(v) * that[c] )[:SEQ]
//   v read from g_uv (cols 1024..2047), strided; o written transposed [b][c][n].
// grid (1024, 4), block 256, dyn smem 98304 B
// ---------------------------------------------------------------------------
__global__ __launch_bounds__(256) void fft_conv_kernel()
{
    extern __shared__ float2 sh[];
    float2* Z  = sh;
    float2* Wt = sh + FFTLEN;
    const int c = blockIdx.x, b = blockIdx.y, tid = threadIdx.x;

    fft_fill_table(Wt, tid);
    for (int j = tid; j < SEQ; j += 256) {
        Z[j]       = make_float2(g_uv[(size_t)(b * SEQ + j) * D2 + D1 + c], 0.0f);
        Z[j + SEQ] = make_float2(0.0f, 0.0f);
    }
    __syncthreads();

    fft_forward(Z, Wt, tid);

    const float2* tc = g_that + (size_t)c * FFTLEN;
    for (int i = tid; i < FFTLEN; i += 256) {
        float2 z = Z[i], w = tc[i];
        Z[i] = make_float2(z.x * w.x - z.y * w.y, z.x * w.y + z.y * w.x);
    }
    __syncthreads();

    fft_inverse(Z, Wt, tid);

    float* orow = g_ot + ((size_t)b * D1 + c) * SEQ;
    for (int j = tid; j < SEQ; j += 256) orow[j] = Z[j].x;
}

// ---------------------------------------------------------------------------
// GEMM 1: g_uv = silu( X[16384,1024] @ W_uv[1024,2048] )
// 128x128 tile, BK=16, 8x8 per thread, 256 threads.
// ---------------------------------------------------------------------------
__global__ __launch_bounds__(256) void gemm_uv_kernel(
    const float* __restrict__ X, const float* __restrict__ Wuv)
{
    __shared__ float As[16][132];
    __shared__ float Bs[16][132];
    const int tid = threadIdx.x;
    const int m0  = blockIdx.y * 128;
    const int n0  = blockIdx.x * 128;
    const int tm  = (tid >> 4) << 3;
    const int tn  = (tid & 15) << 3;

    float acc[8][8];
    #pragma unroll
    for (int i = 0; i < 8; ++i)
        #pragma unroll
        for (int j = 0; j < 8; ++j) acc[i][j] = 0.0f;

    for (int k0 = 0; k0 < EMBED; k0 += 16) {
        #pragma unroll
        for (int r = 0; r < 2; ++r) {
            int f   = tid + (r << 8);
            int row = f >> 2;
            int c4  = (f & 3) << 2;
            float4 av = *(const float4*)(X + (size_t)(m0 + row) * EMBED + k0 + c4);
            As[c4 + 0][row] = av.x; As[c4 + 1][row] = av.y;
            As[c4 + 2][row] = av.z; As[c4 + 3][row] = av.w;
            int rb = f >> 5;
            int cb = (f & 31) << 2;
            *(float4*)&Bs[rb][cb] = *(const float4*)(Wuv + (size_t)(k0 + rb) * D2 + n0 + cb);
        }
        __syncthreads();
        #pragma unroll
        for (int kk = 0; kk < 16; ++kk) {
            float a[8], bb[8];
            *(float4*)&a[0]  = *(const float4*)&As[kk][tm];
            *(float4*)&a[4]  = *(const float4*)&As[kk][tm + 4];
            *(float4*)&bb[0] = *(const float4*)&Bs[kk][tn];
            *(float4*)&bb[4] = *(const float4*)&Bs[kk][tn + 4];
            #pragma unroll
            for (int i = 0; i < 8; ++i)
                #pragma unroll
                for (int j = 0; j < 8; ++j)
                    acc[i][j] += a[i] * bb[j];
        }
        __syncthreads();
    }

    #pragma unroll
    for (int i = 0; i < 8; ++i) {
        #pragma unroll
        for (int j = 0; j < 8; j += 4) {
            float4 o;
            o.x = siluf(acc[i][j + 0]);
            o.y = siluf(acc[i][j + 1]);
            o.z = siluf(acc[i][j + 2]);
            o.w = siluf(acc[i][j + 3]);
            *(float4*)(g_uv + (size_t)(m0 + tm + i) * D2 + n0 + tn + j) = o;
        }
    }
}

// ---------------------------------------------------------------------------
// GEMM 2: out[16384,1024] = (u .* o) @ W_o[1024,1024]
//   u  = g_uv cols [0,1024);  o from g_ot [b][k][n] (read coalesced along n).
//   Gate fused into A-fragment load.
// ---------------------------------------------------------------------------
__global__ __launch_bounds__(256) void gemm_out_kernel(
    const float* __restrict__ Wo, float* __restrict__ out)
{
    __shared__ float Us[16][132];
    __shared__ float Os[16][132];
    __shared__ float Bs[16][132];
    const int tid = threadIdx.x;
    const int m0  = blockIdx.y * 128;
    const int n0  = blockIdx.x * 128;
    const int bb  = m0 >> 12;       // batch index (SEQ = 4096)
    const int j0  = m0 & 4095;      // position within batch
    const int tm  = (tid >> 4) << 3;
    const int tn  = (tid & 15) << 3;

    float acc[8][8];
    #pragma unroll
    for (int i = 0; i < 8; ++i)
        #pragma unroll
        for (int j = 0; j < 8; ++j) acc[i][j] = 0.0f;

    for (int k0 = 0; k0 < D1; k0 += 16) {
        #pragma unroll
        for (int r = 0; r < 2; ++r) {
            int f   = tid + (r << 8);
            int row = f >> 2;
            int c4  = (f & 3) << 2;
            float4 uvv = *(const float4*)(g_uv + (size_t)(m0 + row) * D2 + k0 + c4);
            Us[c4 + 0][row] = uvv.x; Us[c4 + 1][row] = uvv.y;
            Us[c4 + 2][row] = uvv.z; Us[c4 + 3][row] = uvv.w;
            int rb = f >> 5;
            int cb = (f & 31) << 2;
            *(float4*)&Os[rb][cb] = *(const float4*)(g_ot + ((size_t)bb * D1 + k0 + rb) * SEQ + j0 + cb);
            *(float4*)&Bs[rb][cb] = *(const float4*)(Wo + (size_t)(k0 + rb) * D1 + n0 + cb);
        }
        __syncthreads();
        #pragma unroll
        for (int kk = 0; kk < 16; ++kk) {
            float a[8], o[8], bb2[8];
            *(float4*)&a[0]   = *(const float4*)&Us[kk][tm];
            *(float4*)&a[4]   = *(const float4*)&Us[kk][tm + 4];
            *(float4*)&o[0]   = *(const float4*)&Os[kk][tm];
            *(float4*)&o[4]   = *(const float4*)&Os[kk][tm + 4];
            *(float4*)&bb2[0] = *(const float4*)&Bs[kk][tn];
            *(float4*)&bb2[4] = *(const float4*)&Bs[kk][tn + 4];
            #pragma unroll
            for (int i = 0; i < 8; ++i) a[i] *= o[i];
            #pragma unroll
            for (int i = 0; i < 8; ++i)
                #pragma unroll
                for (int j = 0; j < 8; ++j)
                    acc[i][j] += a[i] * bb2[j];
        }
        __syncthreads();
    }

    #pragma unroll
    for (int i = 0; i < 8; ++i) {
        #pragma unroll
        for (int j = 0; j < 8; j += 4) {
            float4 o4;
            o4.x = acc[i][j + 0]; o4.y = acc[i][j + 1];
            o4.z = acc[i][j + 2]; o4.w = acc[i][j + 3];
            *(float4*)(out + (size_t)(m0 + tm + i) * D1 + n0 + tn + j) = o4;
        }
    }
}

// ---------------------------------------------------------------------------
// Launch
// ---------------------------------------------------------------------------
extern "C" void kernel_launch(void* const* d_in, const int* in_sizes, int n_in,
                              void* d_out, int out_size)
{
    const float* x           = (const float*)d_in[0];
    const float* W_uv        = (const float*)d_in[1];
    const float* W_o         = (const float*)d_in[2];
    const float* rpe_in_w    = (const float*)d_in[3];
    const float* rpe_hid_w   = (const float*)d_in[4];
    const float* rpe_ln_g    = (const float*)d_in[5];
    const float* rpe_ln_b    = (const float*)d_in[6];
    const float* rpe_out_w   = (const float*)d_in[7];
    const float* decay_gamma = (const float*)d_in[8];
    float* out = (float*)d_out;

    const int FFT_SMEM = (FFTLEN + SEQ) * (int)sizeof(float2);  // 98304
    cudaFuncSetAttribute(fft_t_kernel,    cudaFuncAttributeMaxDynamicSharedMemorySize, FFT_SMEM);
    cudaFuncSetAttribute(fft_conv_kernel, cudaFuncAttributeMaxDynamicSharedMemorySize, FFT_SMEM);

    rpe_kernel<<<32, 256>>>(rpe_in_w, rpe_hid_w, rpe_ln_g, rpe_ln_b, rpe_out_w, decay_gamma);
    fft_t_kernel<<<D1, 256, FFT_SMEM>>>();
    gemm_uv_kernel<<<dim3(D2 / 128, M_TOT / 128), 256>>>(x, W_uv);
    fft_conv_kernel<<<dim3(D1, BATCH), 256, FFT_SMEM>>>();
    gemm_out_kernel<<<dim3(D1 / 128, M_TOT / 128), 256>>>(W_o, out);
}

// round 2
// speedup vs baseline: 1.4393x; 1.4393x over previous
#include <cuda_runtime.h>
#include <cuda_bf16.h>
#include <cstdint>

// ---------------------------------------------------------------------------
// Problem dims (fixed)
// ---------------------------------------------------------------------------
#define BATCH   4
#define SEQ     4096
#define EMBED   1024
#define D1      1024
#define D2      2048          // 2*D1
#define FEAT    32
#define RPE_L   3
#define FFTLEN  8192          // 2*SEQ
#define M_TOT   (BATCH*SEQ)   // 16384
#define FFT_NT  512           // threads per FFT CTA

// ---------------------------------------------------------------------------
// Scratch (device globals; no runtime allocation allowed)
// ---------------------------------------------------------------------------
__device__ float  g_uv  [(size_t)M_TOT * D2];        // silu(x@W_uv): u = cols [0,1024), v = cols [1024,2048)
__device__ float  g_tT  [(size_t)D1 * SEQ];          // t transposed: [c][k]
__device__ float2 g_that[(size_t)D1 * FFTLEN];       // FFT(t) per channel, DIF bit-reversed order, scaled by 1/L
__device__ float  g_ot  [(size_t)BATCH * D1 * SEQ];  // o transposed: [b][c][n]

__device__ __forceinline__ float siluf(float x) { return x * (1.0f / (1.0f + __expf(-x))); }
__device__ __forceinline__ float2 cmul(float2 a, float2 b) {
    return make_float2(a.x * b.x - a.y * b.y, a.x * b.y + a.y * b.x);
}
__device__ __forceinline__ float2 cmulc(float2 a, float2 b) {   // a * conj(b)
    return make_float2(a.x * b.x + a.y * b.y, a.y * b.x - a.x * b.y);
}
__device__ __forceinline__ float2 cadd(float2 a, float2 b) { return make_float2(a.x + b.x, a.y + b.y); }
__device__ __forceinline__ float2 csub(float2 a, float2 b) { return make_float2(a.x - b.x, a.y - b.y); }
__device__ __forceinline__ int rev13(int i) { return (int)(__brev((unsigned)i) >> 19); }

// ---------------------------------------------------------------------------
// Kernel A: RPE MLP -> t_T[c][k], with per-channel decay gamma^k folded in
// ---------------------------------------------------------------------------
__global__ __launch_bounds__(256) void rpe_kernel(
    const float* __restrict__ in_w,      // [1,32]
    const float* __restrict__ hid_w,     // [3,32,32]
    const float* __restrict__ ln_g,      // [3,32]
    const float* __restrict__ ln_b,      // [3,32]
    const float* __restrict__ out_w,     // [32,1024]
    const float* __restrict__ dgamma)    // [1024]
{
    __shared__ float hsh[128][FEAT + 1];
    const int tid = threadIdx.x;
    const int k0  = blockIdx.x * 128;

    if (tid < 128) {
        float kf = (float)(k0 + tid);
        float h[FEAT], hn[FEAT];
        #pragma unroll
        for (int f = 0; f < FEAT; ++f) h[f] = siluf(kf * in_w[f]);

        for (int layer = 0; layer < RPE_L; ++layer) {
            float mu = 0.0f;
            #pragma unroll
            for (int f = 0; f < FEAT; ++f) mu += h[f];
            mu *= (1.0f / FEAT);
            float var = 0.0f;
            #pragma unroll
            for (int f = 0; f < FEAT; ++f) { float d = h[f] - mu; var += d * d; }
            var *= (1.0f / FEAT);
            float inv = rsqrtf(var + 1e-5f);
            #pragma unroll
            for (int f = 0; f < FEAT; ++f)
                hn[f] = (h[f] - mu) * inv * ln_g[layer * FEAT + f] + ln_b[layer * FEAT + f];
            #pragma unroll
            for (int f2 = 0; f2 < FEAT; ++f2) {
                float acc = 0.0f;
                #pragma unroll
                for (int f = 0; f < FEAT; ++f)
                    acc += hn[f] * hid_w[layer * FEAT * FEAT + f * FEAT + f2];
                h[f2] = siluf(acc);
            }
        }
        #pragma unroll
        for (int f = 0; f < FEAT; ++f) hsh[tid][f] = h[f];
    }
    __syncthreads();

    for (int c = tid; c < D1; c += 256) {
        float w[FEAT];
        #pragma unroll
        for (int f = 0; f < FEAT; ++f) w[f] = out_w[f * D1 + c];
        float g  = 0.99f + 0.01f * (1.0f / (1.0f + __expf(-dgamma[c])));
        float lg = logf(g);
        float dec = expf((float)k0 * lg);
        for (int kk = 0; kk < 128; ++kk) {
            float acc = 0.0f;
            #pragma unroll
            for (int f = 0; f < FEAT; ++f) acc += hsh[kk][f] * w[f];
            g_tT[(size_t)c * SEQ + k0 + kk] = acc * dec;
            dec *= g;
        }
    }
}

// ---------------------------------------------------------------------------
// FFT: length 8192, fused radix-4 (two radix-2 DIF stages combined), output in
// bit-reversed order identical to plain radix-2 DIF. Twiddle table
// Wt[j] = e^{-i pi j / 4096}, j in [0,4096).
// ---------------------------------------------------------------------------
__device__ __forceinline__ void fft_fill_table(float2* Wt, int tid) {
    for (int j = tid; j < SEQ; j += FFT_NT) {
        float s, c;
        sincosf(-3.14159265358979f * (float)j / (float)SEQ, &s, &c);
        Wt[j] = make_float2(c, s);
    }
}

// Forward: natural order in -> bit-reversed out.
__device__ __forceinline__ void fft_forward(float2* Z, const float2* Wt, int tid) {
    #pragma unroll
    for (int s1 = 12; s1 >= 2; s1 -= 2) {
        const int q = 1 << (s1 - 1);
        #pragma unroll 2
        for (int idx = tid; idx < FFTLEN / 4; idx += FFT_NT) {
            int j  = idx & (q - 1);
            int i0 = ((idx - j) << 2) + j;
            float2 a0 = Z[i0], a1 = Z[i0 + q], a2 = Z[i0 + 2 * q], a3 = Z[i0 + 3 * q];
            float2 w  = Wt[j << (12 - s1)];
            float2 w2 = make_float2(w.x * w.x - w.y * w.y, 2.0f * w.x * w.y);
            float2 t02p = cadd(a0, a2);
            float2 t02m = cmul(csub(a0, a2), w);
            float2 t13p = cadd(a1, a3);
            float2 tm   = cmul(csub(a1, a3), w);        // (a1-a3)*w
            float2 t13m = make_float2(tm.y, -tm.x);     // * (-i)
            Z[i0]         = cadd(t02p, t13p);
            Z[i0 + q]     = cmul(csub(t02p, t13p), w2);
            Z[i0 + 2 * q] = cadd(t02m, t13m);
            Z[i0 + 3 * q] = cmul(csub(t02m, t13m), w2);
        }
        __syncthreads();
    }
    // final radix-2 stage (h=1, w=1)
    for (int idx = tid; idx < FFTLEN / 2; idx += FFT_NT) {
        int i0 = idx << 1;
        float2 a = Z[i0], b = Z[i0 + 1];
        Z[i0]     = cadd(a, b);
        Z[i0 + 1] = csub(a, b);
    }
    __syncthreads();
}

// Inverse (unnormalized, gain L): bit-reversed in -> natural out.
__device__ __forceinline__ void fft_inverse(float2* Z, const float2* Wt, int tid) {
    // first radix-2 stage (h=1, w=1)
    for (int idx = tid; idx < FFTLEN / 2; idx += FFT_NT) {
        int i0 = idx << 1;
        float2 a = Z[i0], b = Z[i0 + 1];
        Z[i0]     = cadd(a, b);
        Z[i0 + 1] = csub(a, b);
    }
    __syncthreads();
    #pragma unroll
    for (int s1 = 2; s1 <= 12; s1 += 2) {
        const int q = 1 << (s1 - 1);
        #pragma unroll 2
        for (int idx = tid; idx < FFTLEN / 4; idx += FFT_NT) {
            int j  = idx & (q - 1);
            int i0 = ((idx - j) << 2) + j;
            float2 y0 = Z[i0], y1 = Z[i0 + q], y2 = Z[i0 + 2 * q], y3 = Z[i0 + 3 * q];
            float2 w   = Wt[j << (12 - s1)];
            float2 cw  = make_float2(w.x, -w.y);
            float2 cw2 = make_float2(cw.x * cw.x - cw.y * cw.y, 2.0f * cw.x * cw.y);
            float2 r1 = cmul(y1, cw2);
            float2 r3 = cmul(y3, cw2);
            float2 u0 = cadd(y0, r1), u1 = csub(y0, r1);
            float2 u2 = cadd(y2, r3), u3 = csub(y2, r3);
            float2 t  = cmul(u2, cw);
            float2 sm = cmul(u3, cw);
            float2 si = make_float2(-sm.y, sm.x);       // * (+i)
            Z[i0]         = cadd(u0, t);
            Z[i0 + 2 * q] = csub(u0, t);
            Z[i0 + q]     = cadd(u1, si);
            Z[i0 + 3 * q] = csub(u1, si);
        }
        __syncthreads();
    }
}

// ---------------------------------------------------------------------------
// Kernel B: channel-paired t-FFT. CTA handles channels (2c, 2c+1):
//   Z = t_{c0} + i t_{c1}  -> forward FFT -> Hermitian split -> store both
//   spectra (bit-reversed order, scaled by 1/L).
// grid 512, block 512, dyn smem 98304 B
// ---------------------------------------------------------------------------
__global__ __launch_bounds__(FFT_NT) void fft_t_kernel()
{
    extern __shared__ float2 sh[];
    float2* Z  = sh;           // 8192
    float2* Wt = sh + FFTLEN;  // 4096
    const int c0 = blockIdx.x * 2, c1 = c0 + 1;
    const int tid = threadIdx.x;

    fft_fill_table(Wt, tid);
    const float* t0 = g_tT + (size_t)c0 * SEQ;
    const float* t1 = g_tT + (size_t)c1 * SEQ;
    for (int j = tid; j < SEQ; j += FFT_NT) {
        Z[j]       = make_float2(t0[j], t1[j]);
        Z[j + SEQ] = make_float2(0.0f, 0.0f);
    }
    __syncthreads();

    fft_forward(Z, Wt, tid);

    // Hermitian split: position i holds freq k=rev13(i); partner holds L-k.
    const float sc = 0.5f / (float)FFTLEN;
    float2* o0 = g_that + (size_t)c0 * FFTLEN;
    float2* o1 = g_that + (size_t)c1 * FFTLEN;
    for (int i = tid; i < FFTLEN; i += FFT_NT) {
        int k  = rev13(i);
        int ip = rev13((FFTLEN - k) & (FFTLEN - 1));
        float2 z = Z[i], p = Z[ip];
        // Tc = (z + conj(p))/2 ; Td = (z - conj(p))/(2i)
        o0[i] = make_float2(sc * (z.x + p.x), sc * (z.y - p.y));
        o1[i] = make_float2(sc * (z.y + p.y), sc * (p.x - z.x));
    }
}

// ---------------------------------------------------------------------------
// Kernel C: batch-paired conv. CTA handles (channel c, batches 2b, 2b+1):
//   Z = v[b0][:,c] + i v[b1][:,c] -> forward -> *that[c] -> inverse;
//   Re -> o[b0][c][:], Im -> o[b1][c][:].
// grid (1024, 2), block 512, dyn smem 98304 B
// ---------------------------------------------------------------------------
__global__ __launch_bounds__(FFT_NT) void fft_conv_kernel()
{
    extern __shared__ float2 sh[];
    float2* Z  = sh;
    float2* Wt = sh + FFTLEN;
    const int c  = blockIdx.x;
    const int b0 = blockIdx.y * 2, b1 = b0 + 1;
    const int tid = threadIdx.x;

    fft_fill_table(Wt, tid);
    const float* v0 = g_uv + (size_t)(b0 * SEQ) * D2 + D1 + c;
    const float* v1 = g_uv + (size_t)(b1 * SEQ) * D2 + D1 + c;
    for (int j = tid; j < SEQ; j += FFT_NT) {
        Z[j]       = make_float2(v0[(size_t)j * D2], v1[(size_t)j * D2]);
        Z[j + SEQ] = make_float2(0.0f, 0.0f);
    }
    __syncthreads();

    fft_forward(Z, Wt, tid);

    const float2* tc = g_that + (size_t)c * FFTLEN;
    for (int i = tid; i < FFTLEN; i += FFT_NT)
        Z[i] = cmul(Z[i], tc[i]);
    __syncthreads();

    fft_inverse(Z, Wt, tid);

    float* o0 = g_ot + ((size_t)b0 * D1 + c) * SEQ;
    float* o1 = g_ot + ((size_t)b1 * D1 + c) * SEQ;
    for (int j = tid; j < SEQ; j += FFT_NT) {
        float2 z = Z[j];
        o0[j] = z.x;
        o1[j] = z.y;
    }
}

// ---------------------------------------------------------------------------
// GEMM 1: g_uv = silu( X[16384,1024] @ W_uv[1024,2048] )
// ---------------------------------------------------------------------------
__global__ __launch_bounds__(256) void gemm_uv_kernel(
    const float* __restrict__ X, const float* __restrict__ Wuv)
{
    __shared__ float As[16][132];
    __shared__ float Bs[16][132];
    const int tid = threadIdx.x;
    const int m0  = blockIdx.y * 128;
    const int n0  = blockIdx.x * 128;
    const int tm  = (tid >> 4) << 3;
    const int tn  = (tid & 15) << 3;

    float acc[8][8];
    #pragma unroll
    for (int i = 0; i < 8; ++i)
        #pragma unroll
        for (int j = 0; j < 8; ++j) acc[i][j] = 0.0f;

    for (int k0 = 0; k0 < EMBED; k0 += 16) {
        #pragma unroll
        for (int r = 0; r < 2; ++r) {
            int f   = tid + (r << 8);
            int row = f >> 2;
            int c4  = (f & 3) << 2;
            float4 av = *(const float4*)(X + (size_t)(m0 + row) * EMBED + k0 + c4);
            As[c4 + 0][row] = av.x; As[c4 + 1][row] = av.y;
            As[c4 + 2][row] = av.z; As[c4 + 3][row] = av.w;
            int rb = f >> 5;
            int cb = (f & 31) << 2;
            *(float4*)&Bs[rb][cb] = *(const float4*)(Wuv + (size_t)(k0 + rb) * D2 + n0 + cb);
        }
        __syncthreads();
        #pragma unroll
        for (int kk = 0; kk < 16; ++kk) {
            float a[8], bb[8];
            *(float4*)&a[0]  = *(const float4*)&As[kk][tm];
            *(float4*)&a[4]  = *(const float4*)&As[kk][tm + 4];
            *(float4*)&bb[0] = *(const float4*)&Bs[kk][tn];
            *(float4*)&bb[4] = *(const float4*)&Bs[kk][tn + 4];
            #pragma unroll
            for (int i = 0; i < 8; ++i)
                #pragma unroll
                for (int j = 0; j < 8; ++j)
                    acc[i][j] += a[i] * bb[j];
        }
        __syncthreads();
    }

    #pragma unroll
    for (int i = 0; i < 8; ++i) {
        #pragma unroll
        for (int j = 0; j < 8; j += 4) {
            float4 o;
            o.x = siluf(acc[i][j + 0]);
            o.y = siluf(acc[i][j + 1]);
            o.z = siluf(acc[i][j + 2]);
            o.w = siluf(acc[i][j + 3]);
            *(float4*)(g_uv + (size_t)(m0 + tm + i) * D2 + n0 + tn + j) = o;
        }
    }
}

// ---------------------------------------------------------------------------
// GEMM 2: out[16384,1024] = (u .* o) @ W_o[1024,1024]
// ---------------------------------------------------------------------------
__global__ __launch_bounds__(256) void gemm_out_kernel(
    const float* __restrict__ Wo, float* __restrict__ out)
{
    __shared__ float Us[16][132];
    __shared__ float Os[16][132];
    __shared__ float Bs[16][132];
    const int tid = threadIdx.x;
    const int m0  = blockIdx.y * 128;
    const int n0  = blockIdx.x * 128;
    const int bb  = m0 >> 12;       // batch index (SEQ = 4096)
    const int j0  = m0 & 4095;      // position within batch
    const int tm  = (tid >> 4) << 3;
    const int tn  = (tid & 15) << 3;

    float acc[8][8];
    #pragma unroll
    for (int i = 0; i < 8; ++i)
        #pragma unroll
        for (int j = 0; j < 8; ++j) acc[i][j] = 0.0f;

    for (int k0 = 0; k0 < D1; k0 += 16) {
        #pragma unroll
        for (int r = 0; r < 2; ++r) {
            int f   = tid + (r << 8);
            int row = f >> 2;
            int c4  = (f & 3) << 2;
            float4 uvv = *(const float4*)(g_uv + (size_t)(m0 + row) * D2 + k0 + c4);
            Us[c4 + 0][row] = uvv.x; Us[c4 + 1][row] = uvv.y;
            Us[c4 + 2][row] = uvv.z; Us[c4 + 3][row] = uvv.w;
            int rb = f >> 5;
            int cb = (f & 31) << 2;
            *(float4*)&Os[rb][cb] = *(const float4*)(g_ot + ((size_t)bb * D1 + k0 + rb) * SEQ + j0 + cb);
            *(float4*)&Bs[rb][cb] = *(const float4*)(Wo + (size_t)(k0 + rb) * D1 + n0 + cb);
        }
        __syncthreads();
        #pragma unroll
        for (int kk = 0; kk < 16; ++kk) {
            float a[8], o[8], bb2[8];
            *(float4*)&a[0]   = *(const float4*)&Us[kk][tm];
            *(float4*)&a[4]   = *(const float4*)&Us[kk][tm + 4];
            *(float4*)&o[0]   = *(const float4*)&Os[kk][tm];
            *(float4*)&o[4]   = *(const float4*)&Os[kk][tm + 4];
            *(float4*)&bb2[0] = *(const float4*)&Bs[kk][tn];
            *(float4*)&bb2[4] = *(const float4*)&Bs[kk][tn + 4];
            #pragma unroll
            for (int i = 0; i < 8; ++i) a[i] *= o[i];
            #pragma unroll
            for (int i = 0; i < 8; ++i)
                #pragma unroll
                for (int j = 0; j < 8; ++j)
                    acc[i][j] += a[i] * bb2[j];
        }
        __syncthreads();
    }

    #pragma unroll
    for (int i = 0; i < 8; ++i) {
        #pragma unroll
        for (int j = 0; j < 8; j += 4) {
            float4 o4;
            o4.x = acc[i][j + 0]; o4.y = acc[i][j + 1];
            o4.z = acc[i][j + 2]; o4.w = acc[i][j + 3];
            *(float4*)(out + (size_t)(m0 + tm + i) * D1 + n0 + tn + j) = o4;
        }
    }
}

// ---------------------------------------------------------------------------
// Launch
// ---------------------------------------------------------------------------
extern "C" void kernel_launch(void* const* d_in, const int* in_sizes, int n_in,
                              void* d_out, int out_size)
{
    const float* x           = (const float*)d_in[0];
    const float* W_uv        = (const float*)d_in[1];
    const float* W_o         = (const float*)d_in[2];
    const float* rpe_in_w    = (const float*)d_in[3];
    const float* rpe_hid_w   = (const float*)d_in[4];
    const float* rpe_ln_g    = (const float*)d_in[5];
    const float* rpe_ln_b    = (const float*)d_in[6];
    const float* rpe_out_w   = (const float*)d_in[7];
    const float* decay_gamma = (const float*)d_in[8];
    float* out = (float*)d_out;

    const int FFT_SMEM = (FFTLEN + SEQ) * (int)sizeof(float2);  // 98304
    cudaFuncSetAttribute(fft_t_kernel,    cudaFuncAttributeMaxDynamicSharedMemorySize, FFT_SMEM);
    cudaFuncSetAttribute(fft_conv_kernel, cudaFuncAttributeMaxDynamicSharedMemorySize, FFT_SMEM);

    rpe_kernel<<<32, 256>>>(rpe_in_w, rpe_hid_w, rpe_ln_g, rpe_ln_b, rpe_out_w, decay_gamma);
    fft_t_kernel<<<D1 / 2, FFT_NT, FFT_SMEM>>>();
    gemm_uv_kernel<<<dim3(D2 / 128, M_TOT / 128), 256>>>(x, W_uv);
    fft_conv_kernel<<<dim3(D1, BATCH / 2), FFT_NT, FFT_SMEM>>>();
    gemm_out_kernel<<<dim3(D1 / 128, M_TOT / 128), 256>>>(W_o, out);
}

// round 4
// speedup vs baseline: 2.6903x; 1.8692x over previous
#include <cuda_runtime.h>
#include <cuda_bf16.h>
#include <cstdint>

// ---------------------------------------------------------------------------
// Problem dims (fixed)
// ---------------------------------------------------------------------------
#define BATCH   4
#define SEQ     4096
#define EMBED   1024
#define D1      1024
#define D2      2048          // 2*D1
#define FEAT    32
#define RPE_L   3
#define FFTLEN  8192          // 2*SEQ
#define M_TOT   (BATCH*SEQ)   // 16384
#define FFT_NT  512           // threads per FFT CTA

#define PADA 20               // [m][k] tile stride (16 + 4) -> conflict-free A frags
#define PADB 136              // [k][n] tile stride (128 + 8) -> conflict-free B frags

// ---------------------------------------------------------------------------
// Scratch (device globals; no runtime allocation allowed)
// ---------------------------------------------------------------------------
__device__ float  g_uv  [(size_t)M_TOT * D2];        // silu(x@W_uv): u = cols [0,1024), v = cols [1024,2048)
__device__ float  g_tT  [(size_t)D1 * SEQ];          // t transposed: [c][k]
__device__ float2 g_that[(size_t)D1 * FFTLEN];       // FFT(t) per channel, bit-reversed, scaled 1/L
__device__ float  g_ot  [(size_t)BATCH * D1 * SEQ];  // o transposed: [b][c][n]

__device__ __forceinline__ float siluf(float x) { return x * (1.0f / (1.0f + __expf(-x))); }
__device__ __forceinline__ float2 cmul(float2 a, float2 b) {
    return make_float2(a.x * b.x - a.y * b.y, a.x * b.y + a.y * b.x);
}
__device__ __forceinline__ float2 cadd(float2 a, float2 b) { return make_float2(a.x + b.x, a.y + b.y); }
__device__ __forceinline__ float2 csub(float2 a, float2 b) { return make_float2(a.x - b.x, a.y - b.y); }
__device__ __forceinline__ int rev13(int i) { return (int)(__brev((unsigned)i) >> 19); }

__device__ __forceinline__ uint32_t f2tf32(float f) {
    uint32_t r; asm("cvt.rna.tf32.f32 %0, %1;" : "=r"(r) : "f"(f)); return r;
}
__device__ __forceinline__ void mma_tf32(float* d, const uint32_t* a, const uint32_t* b) {
    asm volatile("mma.sync.aligned.m16n8k8.row.col.f32.tf32.tf32.f32 "
        "{%0,%1,%2,%3}, {%4,%5,%6,%7}, {%8,%9}, {%0,%1,%2,%3};"
        : "+f"(d[0]), "+f"(d[1]), "+f"(d[2]), "+f"(d[3])
        : "r"(a[0]), "r"(a[1]), "r"(a[2]), "r"(a[3]), "r"(b[0]), "r"(b[1]));
}

// ---------------------------------------------------------------------------
// Kernel A: RPE MLP -> t_T[c][k], with per-channel decay gamma^k folded in
// ---------------------------------------------------------------------------
__global__ __launch_bounds__(256) void rpe_kernel(
    const float* __restrict__ in_w, const float* __restrict__ hid_w,
    const float* __restrict__ ln_g, const float* __restrict__ ln_b,
    const float* __restrict__ out_w, const float* __restrict__ dgamma)
{
    __shared__ float hsh[128][FEAT + 1];
    const int tid = threadIdx.x;
    const int k0  = blockIdx.x * 128;

    if (tid < 128) {
        float kf = (float)(k0 + tid);
        float h[FEAT], hn[FEAT];
        #pragma unroll
        for (int f = 0; f < FEAT; ++f) h[f] = siluf(kf * in_w[f]);

        for (int layer = 0; layer < RPE_L; ++layer) {
            float mu = 0.0f;
            #pragma unroll
            for (int f = 0; f < FEAT; ++f) mu += h[f];
            mu *= (1.0f / FEAT);
            float var = 0.0f;
            #pragma unroll
            for (int f = 0; f < FEAT; ++f) { float d = h[f] - mu; var += d * d; }
            var *= (1.0f / FEAT);
            float inv = rsqrtf(var + 1e-5f);
            #pragma unroll
            for (int f = 0; f < FEAT; ++f)
                hn[f] = (h[f] - mu) * inv * ln_g[layer * FEAT + f] + ln_b[layer * FEAT + f];
            #pragma unroll
            for (int f2 = 0; f2 < FEAT; ++f2) {
                float acc = 0.0f;
                #pragma unroll
                for (int f = 0; f < FEAT; ++f)
                    acc += hn[f] * hid_w[layer * FEAT * FEAT + f * FEAT + f2];
                h[f2] = siluf(acc);
            }
        }
        #pragma unroll
        for (int f = 0; f < FEAT; ++f) hsh[tid][f] = h[f];
    }
    __syncthreads();

    for (int c = tid; c < D1; c += 256) {
        float w[FEAT];
        #pragma unroll
        for (int f = 0; f < FEAT; ++f) w[f] = out_w[f * D1 + c];
        float g  = 0.99f + 0.01f * (1.0f / (1.0f + __expf(-dgamma[c])));
        float lg = logf(g);
        float dec = expf((float)k0 * lg);
        for (int kk = 0; kk < 128; ++kk) {
            float acc = 0.0f;
            #pragma unroll
            for (int f = 0; f < FEAT; ++f) acc += hsh[kk][f] * w[f];
            g_tT[(size_t)c * SEQ + k0 + kk] = acc * dec;
            dec *= g;
        }
    }
}

// ---------------------------------------------------------------------------
// FFT: length 8192, fused radix-4 DIF/DIT (bit-reversed intermediate order).
// ---------------------------------------------------------------------------
__device__ __forceinline__ void fft_fill_table(float2* Wt, int tid) {
    for (int j = tid; j < SEQ; j += FFT_NT) {
        float s, c;
        sincosf(-3.14159265358979f * (float)j / (float)SEQ, &s, &c);
        Wt[j] = make_float2(c, s);
    }
}

__device__ __forceinline__ void fft_forward(float2* Z, const float2* Wt, int tid) {
    #pragma unroll
    for (int s1 = 12; s1 >= 2; s1 -= 2) {
        const int q = 1 << (s1 - 1);
        #pragma unroll 2
        for (int idx = tid; idx < FFTLEN / 4; idx += FFT_NT) {
            int j  = idx & (q - 1);
            int i0 = ((idx - j) << 2) + j;
            float2 a0 = Z[i0], a1 = Z[i0 + q], a2 = Z[i0 + 2 * q], a3 = Z[i0 + 3 * q];
            float2 w  = Wt[j << (12 - s1)];
            float2 w2 = make_float2(w.x * w.x - w.y * w.y, 2.0f * w.x * w.y);
            float2 t02p = cadd(a0, a2);
            float2 t02m = cmul(csub(a0, a2), w);
            float2 t13p = cadd(a1, a3);
            float2 tm   = cmul(csub(a1, a3), w);
            float2 t13m = make_float2(tm.y, -tm.x);
            Z[i0]         = cadd(t02p, t13p);
            Z[i0 + q]     = cmul(csub(t02p, t13p), w2);
            Z[i0 + 2 * q] = cadd(t02m, t13m);
            Z[i0 + 3 * q] = cmul(csub(t02m, t13m), w2);
        }
        __syncthreads();
    }
    for (int idx = tid; idx < FFTLEN / 2; idx += FFT_NT) {
        int i0 = idx << 1;
        float2 a = Z[i0], b = Z[i0 + 1];
        Z[i0]     = cadd(a, b);
        Z[i0 + 1] = csub(a, b);
    }
    __syncthreads();
}

__device__ __forceinline__ void fft_inverse(float2* Z, const float2* Wt, int tid) {
    for (int idx = tid; idx < FFTLEN / 2; idx += FFT_NT) {
        int i0 = idx << 1;
        float2 a = Z[i0], b = Z[i0 + 1];
        Z[i0]     = cadd(a, b);
        Z[i0 + 1] = csub(a, b);
    }
    __syncthreads();
    #pragma unroll
    for (int s1 = 2; s1 <= 12; s1 += 2) {
        const int q = 1 << (s1 - 1);
        #pragma unroll 2
        for (int idx = tid; idx < FFTLEN / 4; idx += FFT_NT) {
            int j  = idx & (q - 1);
            int i0 = ((idx - j) << 2) + j;
            float2 y0 = Z[i0], y1 = Z[i0 + q], y2 = Z[i0 + 2 * q], y3 = Z[i0 + 3 * q];
            float2 w   = Wt[j << (12 - s1)];
            float2 cw  = make_float2(w.x, -w.y);
            float2 cw2 = make_float2(cw.x * cw.x - cw.y * cw.y, 2.0f * cw.x * cw.y);
            float2 r1 = cmul(y1, cw2);
            float2 r3 = cmul(y3, cw2);
            float2 u0 = cadd(y0, r1), u1 = csub(y0, r1);
            float2 u2 = cadd(y2, r3), u3 = csub(y2, r3);
            float2 t  = cmul(u2, cw);
            float2 sm = cmul(u3, cw);
            float2 si = make_float2(-sm.y, sm.x);
            Z[i0]         = cadd(u0, t);
            Z[i0 + 2 * q] = csub(u0, t);
            Z[i0 + q]     = cadd(u1, si);
            Z[i0 + 3 * q] = csub(u1, si);
        }
        __syncthreads();
    }
}

// ---------------------------------------------------------------------------
// Kernel B: channel-paired t-FFT with Hermitian split.
// ---------------------------------------------------------------------------
__global__ __launch_bounds__(FFT_NT) void fft_t_kernel()
{
    extern __shared__ float2 sh[];
    float2* Z  = sh;
    float2* Wt = sh + FFTLEN;
    const int c0 = blockIdx.x * 2, c1 = c0 + 1;
    const int tid = threadIdx.x;

    fft_fill_table(Wt, tid);
    const float* t0 = g_tT + (size_t)c0 * SEQ;
    const float* t1 = g_tT + (size_t)c1 * SEQ;
    for (int j = tid; j < SEQ; j += FFT_NT) {
        Z[j]       = make_float2(t0[j], t1[j]);
        Z[j + SEQ] = make_float2(0.0f, 0.0f);
    }
    __syncthreads();

    fft_forward(Z, Wt, tid);

    const float sc = 0.5f / (float)FFTLEN;
    float2* o0 = g_that + (size_t)c0 * FFTLEN;
    float2* o1 = g_that + (size_t)c1 * FFTLEN;
    for (int i = tid; i < FFTLEN; i += FFT_NT) {
        int k  = rev13(i);
        int ip = rev13((FFTLEN - k) & (FFTLEN - 1));
        float2 z = Z[i], p = Z[ip];
        o0[i] = make_float2(sc * (z.x + p.x), sc * (z.y - p.y));
        o1[i] = make_float2(sc * (z.y + p.y), sc * (p.x - z.x));
    }
}

// ---------------------------------------------------------------------------
// Kernel C: batch-paired conv.
// ---------------------------------------------------------------------------
__global__ __launch_bounds__(FFT_NT) void fft_conv_kernel()
{
    extern __shared__ float2 sh[];
    float2* Z  = sh;
    float2* Wt = sh + FFTLEN;
    const int c  = blockIdx.x;
    const int b0 = blockIdx.y * 2, b1 = b0 + 1;
    const int tid = threadIdx.x;

    fft_fill_table(Wt, tid);
    const float* v0 = g_uv + (size_t)(b0 * SEQ) * D2 + D1 + c;
    const float* v1 = g_uv + (size_t)(b1 * SEQ) * D2 + D1 + c;
    for (int j = tid; j < SEQ; j += FFT_NT) {
        Z[j]       = make_float2(v0[(size_t)j * D2], v1[(size_t)j * D2]);
        Z[j + SEQ] = make_float2(0.0f, 0.0f);
    }
    __syncthreads();

    fft_forward(Z, Wt, tid);

    const float2* tc = g_that + (size_t)c * FFTLEN;
    for (int i = tid; i < FFTLEN; i += FFT_NT)
        Z[i] = cmul(Z[i], tc[i]);
    __syncthreads();

    fft_inverse(Z, Wt, tid);

    float* o0 = g_ot + ((size_t)b0 * D1 + c) * SEQ;
    float* o1 = g_ot + ((size_t)b1 * D1 + c) * SEQ;
    for (int j = tid; j < SEQ; j += FFT_NT) {
        float2 z = Z[j];
        o0[j] = z.x;
        o1[j] = z.y;
    }
}

// ---------------------------------------------------------------------------
// GEMM 1 (tf32 tensor cores): g_uv = silu( X[16384,1024] @ W_uv[1024,2048] )
// 128x128x16 CTA tile, 8 warps (2x4), 64x32 warp tile, mma.m16n8k8.
// ---------------------------------------------------------------------------
__global__ __launch_bounds__(256) void gemm_uv_kernel(
    const float* __restrict__ X, const float* __restrict__ Wuv)
{
    __shared__ uint32_t As[128 * PADA];   // [m][k], tf32 bits
    __shared__ uint32_t Bs[16 * PADB];    // [k][n], tf32 bits
    const int tid   = threadIdx.x;
    const int lane  = tid & 31;
    const int wid   = tid >> 5;
    const int warp_m = wid & 1, warp_n = wid >> 1;
    const int gid = lane >> 2, tq = lane & 3;
    const int m0 = blockIdx.y * 128, n0 = blockIdx.x * 128;

    float acc[4][4][4];
    #pragma unroll
    for (int i = 0; i < 4; ++i)
        #pragma unroll
        for (int j = 0; j < 4; ++j)
            #pragma unroll
            for (int r = 0; r < 4; ++r) acc[i][j][r] = 0.0f;

    for (int k0 = 0; k0 < EMBED; k0 += 16) {
        #pragma unroll
        for (int r = 0; r < 2; ++r) {
            int f   = tid + (r << 8);
            int row = f >> 2, c4 = (f & 3) << 2;
            float4 v = *(const float4*)(X + (size_t)(m0 + row) * EMBED + k0 + c4);
            As[row * PADA + c4 + 0] = f2tf32(v.x);
            As[row * PADA + c4 + 1] = f2tf32(v.y);
            As[row * PADA + c4 + 2] = f2tf32(v.z);
            As[row * PADA + c4 + 3] = f2tf32(v.w);
            int rb = f >> 5, cb = (f & 31) << 2;
            float4 w = *(const float4*)(Wuv + (size_t)(k0 + rb) * D2 + n0 + cb);
            Bs[rb * PADB + cb + 0] = f2tf32(w.x);
            Bs[rb * PADB + cb + 1] = f2tf32(w.y);
            Bs[rb * PADB + cb + 2] = f2tf32(w.z);
            Bs[rb * PADB + cb + 3] = f2tf32(w.w);
        }
        __syncthreads();

        #pragma unroll
        for (int ks = 0; ks < 2; ++ks) {
            const int kk = ks << 3;
            uint32_t a[4][4], b[4][2];
            #pragma unroll
            for (int i = 0; i < 4; ++i) {
                int rm = warp_m * 64 + i * 16;
                a[i][0] = As[(rm + gid    ) * PADA + kk + tq];
                a[i][1] = As[(rm + gid + 8) * PADA + kk + tq];
                a[i][2] = As[(rm + gid    ) * PADA + kk + tq + 4];
                a[i][3] = As[(rm + gid + 8) * PADA + kk + tq + 4];
            }
            #pragma unroll
            for (int j = 0; j < 4; ++j) {
                int cn = warp_n * 32 + j * 8;
                b[j][0] = Bs[(kk + tq    ) * PADB + cn + gid];
                b[j][1] = Bs[(kk + tq + 4) * PADB + cn + gid];
            }
            #pragma unroll
            for (int i = 0; i < 4; ++i)
                #pragma unroll
                for (int j = 0; j < 4; ++j)
                    mma_tf32(acc[i][j], a[i], b[j]);
        }
        __syncthreads();
    }

    #pragma unroll
    for (int i = 0; i < 4; ++i) {
        int row = m0 + warp_m * 64 + i * 16 + gid;
        #pragma unroll
        for (int j = 0; j < 4; ++j) {
            int col = n0 + warp_n * 32 + j * 8 + tq * 2;
            float2 lo = make_float2(siluf(acc[i][j][0]), siluf(acc[i][j][1]));
            float2 hi = make_float2(siluf(acc[i][j][2]), siluf(acc[i][j][3]));
            *(float2*)(g_uv + (size_t)row * D2 + col)       = lo;
            *(float2*)(g_uv + (size_t)(row + 8) * D2 + col) = hi;
        }
    }
}

// ---------------------------------------------------------------------------
// GEMM 2 (tf32 tensor cores): out = (u .* o) @ W_o[1024,1024]
//   u from g_uv[m][k] (k contig), o from g_ot[b][k][m] (m contig).
//   Gate applied in registers at fragment load, then cvt to tf32.
// ---------------------------------------------------------------------------
__global__ __launch_bounds__(256) void gemm_out_kernel(
    const float* __restrict__ Wo, float* __restrict__ out)
{
    __shared__ uint32_t Us[128 * PADA];   // [m][k], raw fp32 bits of u
    __shared__ uint32_t Os[16 * PADB];    // [k][m], raw fp32 bits of o
    __shared__ uint32_t Bs[16 * PADB];    // [k][n], tf32 bits of Wo
    const int tid   = threadIdx.x;
    const int lane  = tid & 31;
    const int wid   = tid >> 5;
    const int warp_m = wid & 1, warp_n = wid >> 1;
    const int gid = lane >> 2, tq = lane & 3;
    const int m0 = blockIdx.y * 128, n0 = blockIdx.x * 128;
    const int bb = m0 >> 12;        // batch (SEQ = 4096)
    const int j0 = m0 & 4095;       // position within batch

    float acc[4][4][4];
    #pragma unroll
    for (int i = 0; i < 4; ++i)
        #pragma unroll
        for (int j = 0; j < 4; ++j)
            #pragma unroll
            for (int r = 0; r < 4; ++r) acc[i][j][r] = 0.0f;

    for (int k0 = 0; k0 < D1; k0 += 16) {
        #pragma unroll
        for (int r = 0; r < 2; ++r) {
            int f   = tid + (r << 8);
            int row = f >> 2, c4 = (f & 3) << 2;
            float4 uvv = *(const float4*)(g_uv + (size_t)(m0 + row) * D2 + k0 + c4);
            Us[row * PADA + c4 + 0] = __float_as_uint(uvv.x);
            Us[row * PADA + c4 + 1] = __float_as_uint(uvv.y);
            Us[row * PADA + c4 + 2] = __float_as_uint(uvv.z);
            Us[row * PADA + c4 + 3] = __float_as_uint(uvv.w);
            int rb = f >> 5, cb = (f & 31) << 2;
            float4 ov = *(const float4*)(g_ot + ((size_t)bb * D1 + k0 + rb) * SEQ + j0 + cb);
            *(uint4*)&Os[rb * PADB + cb] = make_uint4(
                __float_as_uint(ov.x), __float_as_uint(ov.y),
                __float_as_uint(ov.z), __float_as_uint(ov.w));
            float4 w = *(const float4*)(Wo + (size_t)(k0 + rb) * D1 + n0 + cb);
            Bs[rb * PADB + cb + 0] = f2tf32(w.x);
            Bs[rb * PADB + cb + 1] = f2tf32(w.y);
            Bs[rb * PADB + cb + 2] = f2tf32(w.z);
            Bs[rb * PADB + cb + 3] = f2tf32(w.w);
        }
        __syncthreads();

        #pragma unroll
        for (int ks = 0; ks < 2; ++ks) {
            const int kk = ks << 3;
            uint32_t a[4][4], b[4][2];
            #pragma unroll
            for (int i = 0; i < 4; ++i) {
                int rm = warp_m * 64 + i * 16;
                float u0 = __uint_as_float(Us[(rm + gid    ) * PADA + kk + tq]);
                float u1 = __uint_as_float(Us[(rm + gid + 8) * PADA + kk + tq]);
                float u2 = __uint_as_float(Us[(rm + gid    ) * PADA + kk + tq + 4]);
                float u3 = __uint_as_float(Us[(rm + gid + 8) * PADA + kk + tq + 4]);
                float o0 = __uint_as_float(Os[(kk + tq    ) * PADB + rm + gid]);
                float o1 = __uint_as_float(Os[(kk + tq    ) * PADB + rm + gid + 8]);
                float o2 = __uint_as_float(Os[(kk + tq + 4) * PADB + rm + gid]);
                float o3 = __uint_as_float(Os[(kk + tq + 4) * PADB + rm + gid + 8]);
                a[i][0] = f2tf32(u0 * o0);
                a[i][1] = f2tf32(u1 * o1);
                a[i][2] = f2tf32(u2 * o2);
                a[i][3] = f2tf32(u3 * o3);
            }
            #pragma unroll
            for (int j = 0; j < 4; ++j) {
                int cn = warp_n * 32 + j * 8;
                b[j][0] = Bs[(kk + tq    ) * PADB + cn + gid];
                b[j][1] = Bs[(kk + tq + 4) * PADB + cn + gid];
            }
            #pragma unroll
            for (int i = 0; i < 4; ++i)
                #pragma unroll
                for (int j = 0; j < 4; ++j)
                    mma_tf32(acc[i][j], a[i], b[j]);
        }
        __syncthreads();
    }

    #pragma unroll
    for (int i = 0; i < 4; ++i) {
        int row = m0 + warp_m * 64 + i * 16 + gid;
        #pragma unroll
        for (int j = 0; j < 4; ++j) {
            int col = n0 + warp_n * 32 + j * 8 + tq * 2;
            *(float2*)(out + (size_t)row * D1 + col)       = make_float2(acc[i][j][0], acc[i][j][1]);
            *(float2*)(out + (size_t)(row + 8) * D1 + col) = make_float2(acc[i][j][2], acc[i][j][3]);
        }
    }
}

// ---------------------------------------------------------------------------
// Launch
// ---------------------------------------------------------------------------
extern "C" void kernel_launch(void* const* d_in, const int* in_sizes, int n_in,
                              void* d_out, int out_size)
{
    const float* x           = (const float*)d_in[0];
    const float* W_uv        = (const float*)d_in[1];
    const float* W_o         = (const float*)d_in[2];
    const float* rpe_in_w    = (const float*)d_in[3];
    const float* rpe_hid_w   = (const float*)d_in[4];
    const float* rpe_ln_g    = (const float*)d_in[5];
    const float* rpe_ln_b    = (const float*)d_in[6];
    const float* rpe_out_w   = (const float*)d_in[7];
    const float* decay_gamma = (const float*)d_in[8];
    float* out = (float*)d_out;

    const int FFT_SMEM = (FFTLEN + SEQ) * (int)sizeof(float2);  // 98304
    cudaFuncSetAttribute(fft_t_kernel,    cudaFuncAttributeMaxDynamicSharedMemorySize, FFT_SMEM);
    cudaFuncSetAttribute(fft_conv_kernel, cudaFuncAttributeMaxDynamicSharedMemorySize, FFT_SMEM);

    rpe_kernel<<<32, 256>>>(rpe_in_w, rpe_hid_w, rpe_ln_g, rpe_ln_b, rpe_out_w, decay_gamma);
    fft_t_kernel<<<D1 / 2, FFT_NT, FFT_SMEM>>>();
    gemm_uv_kernel<<<dim3(D2 / 128, M_TOT / 128), 256>>>(x, W_uv);
    fft_conv_kernel<<<dim3(D1, BATCH / 2), FFT_NT, FFT_SMEM>>>();
    gemm_out_kernel<<<dim3(D1 / 128, M_TOT / 128), 256>>>(W_o, out);
}

// round 5
// speedup vs baseline: 2.9482x; 1.0959x over previous
#include <cuda_runtime.h>
#include <cuda_bf16.h>
#include <cstdint>

// ---------------------------------------------------------------------------
// Problem dims (fixed)
// ---------------------------------------------------------------------------
#define BATCH   4
#define SEQ     4096
#define EMBED   1024
#define D1      1024
#define D2      2048          // 2*D1
#define FEAT    32
#define RPE_L   3
#define FFTLEN  8192          // 2*SEQ
#define M_TOT   (BATCH*SEQ)   // 16384
#define FFT_NT  512           // threads per FFT CTA

#define PADA 20               // [m][k] tile stride (16 + 4) -> conflict-free A frags
#define PADB 136              // [k][n] tile stride (128 + 8) -> conflict-free B frags
#define ASZ  (128 * PADA)     // 2560 words
#define BSZ  (16 * PADB)      // 2176 words

// ---------------------------------------------------------------------------
// Scratch (device globals; no runtime allocation allowed)
// ---------------------------------------------------------------------------
__device__ __align__(256) float  g_uv  [(size_t)M_TOT * D2];        // u | v
__device__ __align__(256) float  g_tT  [(size_t)D1 * SEQ];          // t transposed [c][k]
__device__ __align__(256) float2 g_that[(size_t)D1 * FFTLEN];       // FFT(t), bit-reversed, 1/L
__device__ __align__(256) float  g_ot  [(size_t)BATCH * D1 * SEQ];  // o transposed [b][c][n]

__device__ __forceinline__ float siluf(float x) { return x * (1.0f / (1.0f + __expf(-x))); }
__device__ __forceinline__ float2 cmul(float2 a, float2 b) {
    return make_float2(a.x * b.x - a.y * b.y, a.x * b.y + a.y * b.x);
}
__device__ __forceinline__ float2 csq(float2 a) {
    return make_float2(a.x * a.x - a.y * a.y, 2.0f * a.x * a.y);
}
__device__ __forceinline__ float2 cadd(float2 a, float2 b) { return make_float2(a.x + b.x, a.y + b.y); }
__device__ __forceinline__ float2 csub(float2 a, float2 b) { return make_float2(a.x - b.x, a.y - b.y); }
__device__ __forceinline__ float2 mulnegi(float2 a) { return make_float2(a.y, -a.x); }   // * (-i)
__device__ __forceinline__ float2 mulposi(float2 a) { return make_float2(-a.y, a.x); }   // * (+i)
__device__ __forceinline__ int rev13(int i) { return (int)(__brev((unsigned)i) >> 19); }

__device__ __forceinline__ uint32_t f2tf32(float f) {
    uint32_t r; asm("cvt.rna.tf32.f32 %0, %1;" : "=r"(r) : "f"(f)); return r;
}
__device__ __forceinline__ void mma_tf32(float* d, const uint32_t* a, const uint32_t* b) {
    asm volatile("mma.sync.aligned.m16n8k8.row.col.f32.tf32.tf32.f32 "
        "{%0,%1,%2,%3}, {%4,%5,%6,%7}, {%8,%9}, {%0,%1,%2,%3};"
        : "+f"(d[0]), "+f"(d[1]), "+f"(d[2]), "+f"(d[3])
        : "r"(a[0]), "r"(a[1]), "r"(a[2]), "r"(a[3]), "r"(b[0]), "r"(b[1]));
}
__device__ __forceinline__ void cp_async16(void* smem, const void* gmem) {
    uint32_t s = (uint32_t)__cvta_generic_to_shared(smem);
    asm volatile("cp.async.cg.shared.global [%0], [%1], 16;\n" :: "r"(s), "l"(gmem));
}
#define CP_COMMIT() asm volatile("cp.async.commit_group;\n" ::: "memory")
#define CP_WAIT0()  asm volatile("cp.async.wait_group 0;\n" ::: "memory")

// ---------------------------------------------------------------------------
// Kernel A: RPE MLP -> t_T[c][k], with per-channel decay gamma^k folded in
// ---------------------------------------------------------------------------
__global__ __launch_bounds__(256) void rpe_kernel(
    const float* __restrict__ in_w, const float* __restrict__ hid_w,
    const float* __restrict__ ln_g, const float* __restrict__ ln_b,
    const float* __restrict__ out_w, const float* __restrict__ dgamma)
{
    __shared__ float hsh[128][FEAT + 1];
    const int tid = threadIdx.x;
    const int k0  = blockIdx.x * 128;

    if (tid < 128) {
        float kf = (float)(k0 + tid);
        float h[FEAT], hn[FEAT];
        #pragma unroll
        for (int f = 0; f < FEAT; ++f) h[f] = siluf(kf * in_w[f]);

        for (int layer = 0; layer < RPE_L; ++layer) {
            float mu = 0.0f;
            #pragma unroll
            for (int f = 0; f < FEAT; ++f) mu += h[f];
            mu *= (1.0f / FEAT);
            float var = 0.0f;
            #pragma unroll
            for (int f = 0; f < FEAT; ++f) { float d = h[f] - mu; var += d * d; }
            var *= (1.0f / FEAT);
            float inv = rsqrtf(var + 1e-5f);
            #pragma unroll
            for (int f = 0; f < FEAT; ++f)
                hn[f] = (h[f] - mu) * inv * ln_g[layer * FEAT + f] + ln_b[layer * FEAT + f];
            #pragma unroll
            for (int f2 = 0; f2 < FEAT; ++f2) {
                float acc = 0.0f;
                #pragma unroll
                for (int f = 0; f < FEAT; ++f)
                    acc += hn[f] * hid_w[layer * FEAT * FEAT + f * FEAT + f2];
                h[f2] = siluf(acc);
            }
        }
        #pragma unroll
        for (int f = 0; f < FEAT; ++f) hsh[tid][f] = h[f];
    }
    __syncthreads();

    for (int c = tid; c < D1; c += 256) {
        float w[FEAT];
        #pragma unroll
        for (int f = 0; f < FEAT; ++f) w[f] = out_w[f * D1 + c];
        float g  = 0.99f + 0.01f * (1.0f / (1.0f + __expf(-dgamma[c])));
        float lg = logf(g);
        float dec = expf((float)k0 * lg);
        for (int kk = 0; kk < 128; ++kk) {
            float acc = 0.0f;
            #pragma unroll
            for (int f = 0; f < FEAT; ++f) acc += hsh[kk][f] * w[f];
            g_tT[(size_t)c * SEQ + k0 + kk] = acc * dec;
            dec *= g;
        }
    }
}

// ---------------------------------------------------------------------------
// FFT: length 8192 = 2^13, fused radix-8 (3 radix-2 DIF stages combined).
// Stage structure: s = 12, 9, 6, 3 (radix-8) + s = 0 (radix-2).
// Output permutation identical to plain radix-2 DIF bit reversal.
// Twiddle table Wt[j] = e^{-i pi j / 4096}, j in [0,4096).
// ---------------------------------------------------------------------------
#define C8R 0.70710678118654752f   // cos(pi/4)

__device__ __forceinline__ void fft_fill_table(float2* Wt, int tid) {
    for (int j = tid; j < SEQ; j += FFT_NT) {
        float s, c;
        sincosf(-3.14159265358979f * (float)j / (float)SEQ, &s, &c);
        Wt[j] = make_float2(c, s);
    }
}

__device__ __forceinline__ void fft_forward(float2* Z, const float2* Wt, int tid) {
    const float2 C8 = make_float2(C8R, -C8R);   // e^{-i pi/4}
    #pragma unroll
    for (int s1 = 12; s1 >= 3; s1 -= 3) {
        const int q = 1 << (s1 - 2);
        #pragma unroll 2
        for (int idx = tid; idx < FFTLEN / 8; idx += FFT_NT) {
            int j  = idx & (q - 1);
            int i0 = ((idx - j) << 3) + j;
            float2 x0 = Z[i0],         x1 = Z[i0 + q],     x2 = Z[i0 + 2 * q], x3 = Z[i0 + 3 * q];
            float2 x4 = Z[i0 + 4 * q], x5 = Z[i0 + 5 * q], x6 = Z[i0 + 6 * q], x7 = Z[i0 + 7 * q];
            float2 w   = Wt[j << (12 - s1)];
            float2 w2  = csq(w);
            float2 w4  = csq(w2);
            float2 wc8 = cmul(w, C8);
            // stage 1 (h = 4q):  y_{k+4} = (x_k - x_{k+4}) * w * e^{-i pi k/4}
            float2 y0 = cadd(x0, x4), y1 = cadd(x1, x5), y2 = cadd(x2, x6), y3 = cadd(x3, x7);
            float2 y4 = cmul(csub(x0, x4), w);
            float2 y5 = cmul(csub(x1, x5), wc8);
            float2 y6 = mulnegi(cmul(csub(x2, x6), w));
            float2 y7 = mulnegi(cmul(csub(x3, x7), wc8));
            // stage 2 (h = 2q):  z_{k+2} = (y_k - y_{k+2}) * w2 * (k odd ? -i : 1)
            float2 z0 = cadd(y0, y2), z2 = cmul(csub(y0, y2), w2);
            float2 z1 = cadd(y1, y3), z3 = mulnegi(cmul(csub(y1, y3), w2));
            float2 z4 = cadd(y4, y6), z6 = cmul(csub(y4, y6), w2);
            float2 z5 = cadd(y5, y7), z7 = mulnegi(cmul(csub(y5, y7), w2));
            // stage 3 (h = q):   out_{k+1} = (z_k - z_{k+1}) * w4
            Z[i0]         = cadd(z0, z1);  Z[i0 + q]     = cmul(csub(z0, z1), w4);
            Z[i0 + 2 * q] = cadd(z2, z3);  Z[i0 + 3 * q] = cmul(csub(z2, z3), w4);
            Z[i0 + 4 * q] = cadd(z4, z5);  Z[i0 + 5 * q] = cmul(csub(z4, z5), w4);
            Z[i0 + 6 * q] = cadd(z6, z7);  Z[i0 + 7 * q] = cmul(csub(z6, z7), w4);
        }
        __syncthreads();
    }
    // final radix-2 stage (h = 1, w = 1)
    for (int idx = tid; idx < FFTLEN / 2; idx += FFT_NT) {
        int i0 = idx << 1;
        float2 a = Z[i0], b = Z[i0 + 1];
        Z[i0]     = cadd(a, b);
        Z[i0 + 1] = csub(a, b);
    }
    __syncthreads();
}

__device__ __forceinline__ void fft_inverse(float2* Z, const float2* Wt, int tid) {
    const float2 CC8 = make_float2(C8R, C8R);   // e^{+i pi/4}
    // first radix-2 stage (h = 1, w = 1)
    for (int idx = tid; idx < FFTLEN / 2; idx += FFT_NT) {
        int i0 = idx << 1;
        float2 a = Z[i0], b = Z[i0 + 1];
        Z[i0]     = cadd(a, b);
        Z[i0 + 1] = csub(a, b);
    }
    __syncthreads();
    #pragma unroll
    for (int s1 = 3; s1 <= 12; s1 += 3) {
        const int q = 1 << (s1 - 2);
        #pragma unroll 2
        for (int idx = tid; idx < FFTLEN / 8; idx += FFT_NT) {
            int j  = idx & (q - 1);
            int i0 = ((idx - j) << 3) + j;
            float2 o0 = Z[i0],         o1 = Z[i0 + q],     o2 = Z[i0 + 2 * q], o3 = Z[i0 + 3 * q];
            float2 o4 = Z[i0 + 4 * q], o5 = Z[i0 + 5 * q], o6 = Z[i0 + 6 * q], o7 = Z[i0 + 7 * q];
            float2 w    = Wt[j << (12 - s1)];
            float2 cw   = make_float2(w.x, -w.y);
            float2 cw2  = csq(cw);
            float2 cw4  = csq(cw2);
            float2 cwc8 = cmul(cw, CC8);
            // stage 3 inverse (pairs k,k+1; twiddle conj(w4))
            float2 t;
            t = cmul(o1, cw4); float2 z0 = cadd(o0, t), z1 = csub(o0, t);
            t = cmul(o3, cw4); float2 z2 = cadd(o2, t), z3 = csub(o2, t);
            t = cmul(o5, cw4); float2 z4 = cadd(o4, t), z5 = csub(o4, t);
            t = cmul(o7, cw4); float2 z6 = cadd(o6, t), z7 = csub(o6, t);
            // stage 2 inverse (pairs k,k+2; twiddle conj(w2), odd k gets +i)
            t = cmul(z2, cw2);          float2 y0 = cadd(z0, t), y2 = csub(z0, t);
            t = mulposi(cmul(z3, cw2)); float2 y1 = cadd(z1, t), y3 = csub(z1, t);
            t = cmul(z6, cw2);          float2 y4 = cadd(z4, t), y6 = csub(z4, t);
            t = mulposi(cmul(z7, cw2)); float2 y5 = cadd(z5, t), y7 = csub(z5, t);
            // stage 1 inverse (pairs k,k+4; twiddle conj(w * e^{-i pi k/4}))
            t = cmul(y4, cw);            Z[i0]         = cadd(y0, t); Z[i0 + 4 * q] = csub(y0, t);
            t = cmul(y5, cwc8);          Z[i0 + q]     = cadd(y1, t); Z[i0 + 5 * q] = csub(y1, t);
            t = mulposi(cmul(y6, cw));   Z[i0 + 2 * q] = cadd(y2, t); Z[i0 + 6 * q] = csub(y2, t);
            t = mulposi(cmul(y7, cwc8)); Z[i0 + 3 * q] = cadd(y3, t); Z[i0 + 7 * q] = csub(y3, t);
        }
        __syncthreads();
    }
}

// ---------------------------------------------------------------------------
// Kernel B: channel-paired t-FFT with Hermitian split.
// ---------------------------------------------------------------------------
__global__ __launch_bounds__(FFT_NT) void fft_t_kernel()
{
    extern __shared__ float2 sh[];
    float2* Z  = sh;
    float2* Wt = sh + FFTLEN;
    const int c0 = blockIdx.x * 2, c1 = c0 + 1;
    const int tid = threadIdx.x;

    fft_fill_table(Wt, tid);
    const float* t0 = g_tT + (size_t)c0 * SEQ;
    const float* t1 = g_tT + (size_t)c1 * SEQ;
    for (int j = tid; j < SEQ; j += FFT_NT) {
        Z[j]       = make_float2(t0[j], t1[j]);
        Z[j + SEQ] = make_float2(0.0f, 0.0f);
    }
    __syncthreads();

    fft_forward(Z, Wt, tid);

    const float sc = 0.5f / (float)FFTLEN;
    float2* o0 = g_that + (size_t)c0 * FFTLEN;
    float2* o1 = g_that + (size_t)c1 * FFTLEN;
    for (int i = tid; i < FFTLEN; i += FFT_NT) {
        int k  = rev13(i);
        int ip = rev13((FFTLEN - k) & (FFTLEN - 1));
        float2 z = Z[i], p = Z[ip];
        o0[i] = make_float2(sc * (z.x + p.x), sc * (z.y - p.y));
        o1[i] = make_float2(sc * (z.y + p.y), sc * (p.x - z.x));
    }
}

// ---------------------------------------------------------------------------
// Kernel C: batch-paired conv.
// ---------------------------------------------------------------------------
__global__ __launch_bounds__(FFT_NT) void fft_conv_kernel()
{
    extern __shared__ float2 sh[];
    float2* Z  = sh;
    float2* Wt = sh + FFTLEN;
    const int c  = blockIdx.x;
    const int b0 = blockIdx.y * 2, b1 = b0 + 1;
    const int tid = threadIdx.x;

    fft_fill_table(Wt, tid);
    const float* v0 = g_uv + (size_t)(b0 * SEQ) * D2 + D1 + c;
    const float* v1 = g_uv + (size_t)(b1 * SEQ) * D2 + D1 + c;
    for (int j = tid; j < SEQ; j += FFT_NT) {
        Z[j]       = make_float2(v0[(size_t)j * D2], v1[(size_t)j * D2]);
        Z[j + SEQ] = make_float2(0.0f, 0.0f);
    }
    __syncthreads();

    fft_forward(Z, Wt, tid);

    const float2* tc = g_that + (size_t)c * FFTLEN;
    for (int i = tid; i < FFTLEN; i += FFT_NT)
        Z[i] = cmul(Z[i], tc[i]);
    __syncthreads();

    fft_inverse(Z, Wt, tid);

    float* o0 = g_ot + ((size_t)b0 * D1 + c) * SEQ;
    float* o1 = g_ot + ((size_t)b1 * D1 + c) * SEQ;
    for (int j = tid; j < SEQ; j += FFT_NT) {
        float2 z = Z[j];
        o0[j] = z.x;
        o1[j] = z.y;
    }
}

// ---------------------------------------------------------------------------
// GEMM 1 (tf32 + cp.async double buffering):
//   g_uv = silu( X[16384,1024] @ W_uv[1024,2048] )
// ---------------------------------------------------------------------------
__global__ __launch_bounds__(256) void gemm_uv_kernel(
    const float* __restrict__ X, const float* __restrict__ Wuv)
{
    __shared__ uint32_t As[2][ASZ];   // [m][k] raw fp32 bits
    __shared__ uint32_t Bs[2][BSZ];   // [k][n] raw fp32 bits
    const int tid   = threadIdx.x;
    const int lane  = tid & 31;
    const int wid   = tid >> 5;
    const int warp_m = wid & 1, warp_n = wid >> 1;
    const int gid = lane >> 2, tq = lane & 3;
    const int m0 = blockIdx.y * 128, n0 = blockIdx.x * 128;

    float acc[4][4][4];
    #pragma unroll
    for (int i = 0; i < 4; ++i)
        #pragma unroll
        for (int j = 0; j < 4; ++j)
            #pragma unroll
            for (int r = 0; r < 4; ++r) acc[i][j][r] = 0.0f;

    auto issue_tile = [&](int k0, int buf) {
        #pragma unroll
        for (int r = 0; r < 2; ++r) {
            int f   = tid + (r << 8);
            int row = f >> 2, c4 = (f & 3) << 2;
            cp_async16(&As[buf][row * PADA + c4],
                       X + (size_t)(m0 + row) * EMBED + k0 + c4);
            int rb = f >> 5, cb = (f & 31) << 2;
            cp_async16(&Bs[buf][rb * PADB + cb],
                       Wuv + (size_t)(k0 + rb) * D2 + n0 + cb);
        }
    };

    issue_tile(0, 0);
    CP_COMMIT();

    const int KT = EMBED / 16;
    for (int kt = 0; kt < KT; ++kt) {
        CP_WAIT0();
        __syncthreads();
        if (kt + 1 < KT) { issue_tile((kt + 1) * 16, (kt + 1) & 1); CP_COMMIT(); }
        const uint32_t* A = As[kt & 1];
        const uint32_t* B = Bs[kt & 1];
        #pragma unroll
        for (int ks = 0; ks < 2; ++ks) {
            const int kk = ks << 3;
            uint32_t a[4][4], b[4][2];
            #pragma unroll
            for (int i = 0; i < 4; ++i) {
                int rm = warp_m * 64 + i * 16;
                a[i][0] = f2tf32(__uint_as_float(A[(rm + gid    ) * PADA + kk + tq]));
                a[i][1] = f2tf32(__uint_as_float(A[(rm + gid + 8) * PADA + kk + tq]));
                a[i][2] = f2tf32(__uint_as_float(A[(rm + gid    ) * PADA + kk + tq + 4]));
                a[i][3] = f2tf32(__uint_as_float(A[(rm + gid + 8) * PADA + kk + tq + 4]));
            }
            #pragma unroll
            for (int j = 0; j < 4; ++j) {
                int cn = warp_n * 32 + j * 8;
                b[j][0] = f2tf32(__uint_as_float(B[(kk + tq    ) * PADB + cn + gid]));
                b[j][1] = f2tf32(__uint_as_float(B[(kk + tq + 4) * PADB + cn + gid]));
            }
            #pragma unroll
            for (int i = 0; i < 4; ++i)
                #pragma unroll
                for (int j = 0; j < 4; ++j)
                    mma_tf32(acc[i][j], a[i], b[j]);
        }
        __syncthreads();
    }

    #pragma unroll
    for (int i = 0; i < 4; ++i) {
        int row = m0 + warp_m * 64 + i * 16 + gid;
        #pragma unroll
        for (int j = 0; j < 4; ++j) {
            int col = n0 + warp_n * 32 + j * 8 + tq * 2;
            float2 lo = make_float2(siluf(acc[i][j][0]), siluf(acc[i][j][1]));
            float2 hi = make_float2(siluf(acc[i][j][2]), siluf(acc[i][j][3]));
            *(float2*)(g_uv + (size_t)row * D2 + col)       = lo;
            *(float2*)(g_uv + (size_t)(row + 8) * D2 + col) = hi;
        }
    }
}

// ---------------------------------------------------------------------------
// GEMM 2 (tf32 + cp.async double buffering): out = (u .* o) @ W_o[1024,1024]
//   Dynamic smem: 2 x (Us + Os + Bs) = 55296 B.
// ---------------------------------------------------------------------------
__global__ __launch_bounds__(256) void gemm_out_kernel(
    const float* __restrict__ Wo, float* __restrict__ out)
{
    extern __shared__ uint32_t dsm[];
    uint32_t* Us = dsm;                    // 2 x ASZ, [m][k] bits of u
    uint32_t* Os = dsm + 2 * ASZ;          // 2 x BSZ, [k][m] bits of o
    uint32_t* Bs = dsm + 2 * ASZ + 2 * BSZ;// 2 x BSZ, [k][n] bits of Wo
    const int tid   = threadIdx.x;
    const int lane  = tid & 31;
    const int wid   = tid >> 5;
    const int warp_m = wid & 1, warp_n = wid >> 1;
    const int gid = lane >> 2, tq = lane & 3;
    const int m0 = blockIdx.y * 128, n0 = blockIdx.x * 128;
    const int bb = m0 >> 12;        // batch (SEQ = 4096)
    const int j0 = m0 & 4095;       // position within batch

    float acc[4][4][4];
    #pragma unroll
    for (int i = 0; i < 4; ++i)
        #pragma unroll
        for (int j = 0; j < 4; ++j)
            #pragma unroll
            for (int r = 0; r < 4; ++r) acc[i][j][r] = 0.0f;

    auto issue_tile = [&](int k0, int buf) {
        #pragma unroll
        for (int r = 0; r < 2; ++r) {
            int f   = tid + (r << 8);
            int row = f >> 2, c4 = (f & 3) << 2;
            cp_async16(&Us[buf * ASZ + row * PADA + c4],
                       g_uv + (size_t)(m0 + row) * D2 + k0 + c4);
            int rb = f >> 5, cb = (f & 31) << 2;
            cp_async16(&Os[buf * BSZ + rb * PADB + cb],
                       g_ot + ((size_t)bb * D1 + k0 + rb) * SEQ + j0 + cb);
            cp_async16(&Bs[buf * BSZ + rb * PADB + cb],
                       Wo + (size_t)(k0 + rb) * D1 + n0 + cb);
        }
    };

    issue_tile(0, 0);
    CP_COMMIT();

    const int KT = D1 / 16;
    for (int kt = 0; kt < KT; ++kt) {
        CP_WAIT0();
        __syncthreads();
        if (kt + 1 < KT) { issue_tile((kt + 1) * 16, (kt + 1) & 1); CP_COMMIT(); }
        const uint32_t* U = Us + (kt & 1) * ASZ;
        const uint32_t* O = Os + (kt & 1) * BSZ;
        const uint32_t* B = Bs + (kt & 1) * BSZ;
        #pragma unroll
        for (int ks = 0; ks < 2; ++ks) {
            const int kk = ks << 3;
            uint32_t a[4][4], b[4][2];
            #pragma unroll
            for (int i = 0; i < 4; ++i) {
                int rm = warp_m * 64 + i * 16;
                float u0 = __uint_as_float(U[(rm + gid    ) * PADA + kk + tq]);
                float u1 = __uint_as_float(U[(rm + gid + 8) * PADA + kk + tq]);
                float u2 = __uint_as_float(U[(rm + gid    ) * PADA + kk + tq + 4]);
                float u3 = __uint_as_float(U[(rm + gid + 8) * PADA + kk + tq + 4]);
                float o0 = __uint_as_float(O[(kk + tq    ) * PADB + rm + gid]);
                float o1 = __uint_as_float(O[(kk + tq    ) * PADB + rm + gid + 8]);
                float o2 = __uint_as_float(O[(kk + tq + 4) * PADB + rm + gid]);
                float o3 = __uint_as_float(O[(kk + tq + 4) * PADB + rm + gid + 8]);
                a[i][0] = f2tf32(u0 * o0);
                a[i][1] = f2tf32(u1 * o1);
                a[i][2] = f2tf32(u2 * o2);
                a[i][3] = f2tf32(u3 * o3);
            }
            #pragma unroll
            for (int j = 0; j < 4; ++j) {
                int cn = warp_n * 32 + j * 8;
                b[j][0] = f2tf32(__uint_as_float(B[(kk + tq    ) * PADB + cn + gid]));
                b[j][1] = f2tf32(__uint_as_float(B[(kk + tq + 4) * PADB + cn + gid]));
            }
            #pragma unroll
            for (int i = 0; i < 4; ++i)
                #pragma unroll
                for (int j = 0; j < 4; ++j)
                    mma_tf32(acc[i][j], a[i], b[j]);
        }
        __syncthreads();
    }

    #pragma unroll
    for (int i = 0; i < 4; ++i) {
        int row = m0 + warp_m * 64 + i * 16 + gid;
        #pragma unroll
        for (int j = 0; j < 4; ++j) {
            int col = n0 + warp_n * 32 + j * 8 + tq * 2;
            *(float2*)(out + (size_t)row * D1 + col)       = make_float2(acc[i][j][0], acc[i][j][1]);
            *(float2*)(out + (size_t)(row + 8) * D1 + col) = make_float2(acc[i][j][2], acc[i][j][3]);
        }
    }
}

// ---------------------------------------------------------------------------
// Launch
// ---------------------------------------------------------------------------
extern "C" void kernel_launch(void* const* d_in, const int* in_sizes, int n_in,
                              void* d_out, int out_size)
{
    const float* x           = (const float*)d_in[0];
    const float* W_uv        = (const float*)d_in[1];
    const float* W_o         = (const float*)d_in[2];
    const float* rpe_in_w    = (const float*)d_in[3];
    const float* rpe_hid_w   = (const float*)d_in[4];
    const float* rpe_ln_g    = (const float*)d_in[5];
    const float* rpe_ln_b    = (const float*)d_in[6];
    const float* rpe_out_w   = (const float*)d_in[7];
    const float* decay_gamma = (const float*)d_in[8];
    float* out = (float*)d_out;

    const int FFT_SMEM  = (FFTLEN + SEQ) * (int)sizeof(float2);       // 98304
    const int GEMM2_SMEM = (2 * ASZ + 4 * BSZ) * (int)sizeof(uint32_t); // 55296
    cudaFuncSetAttribute(fft_t_kernel,    cudaFuncAttributeMaxDynamicSharedMemorySize, FFT_SMEM);
    cudaFuncSetAttribute(fft_conv_kernel, cudaFuncAttributeMaxDynamicSharedMemorySize, FFT_SMEM);
    cudaFuncSetAttribute(gemm_out_kernel, cudaFuncAttributeMaxDynamicSharedMemorySize, GEMM2_SMEM);

    rpe_kernel<<<32, 256>>>(rpe_in_w, rpe_hid_w, rpe_ln_g, rpe_ln_b, rpe_out_w, decay_gamma);
    fft_t_kernel<<<D1 / 2, FFT_NT, FFT_SMEM>>>();
    gemm_uv_kernel<<<dim3(D2 / 128, M_TOT / 128), 256>>>(x, W_uv);
    fft_conv_kernel<<<dim3(D1, BATCH / 2), FFT_NT, FFT_SMEM>>>();
    gemm_out_kernel<<<dim3(D1 / 128, M_TOT / 128), 256, GEMM2_SMEM>>>(W_o, out);
}